// round 3
// baseline (speedup 1.0000x reference)
#include <cuda_runtime.h>
#include <cstdint>

#define N_NODES   100000
#define N_EDGES   1600000
#define IN_FEATS  64
#define OUT_FEATS 32

// Scratch (no cudaMalloc allowed)
__device__ float g_hW[N_NODES * OUT_FEATS];   // 12.8 MB
__device__ float g_deg[N_NODES];              // 0.4 MB

// ---------------------------------------------------------------------------
// Packed f32x2 helpers (Blackwell FFMA2 path)
// ---------------------------------------------------------------------------
__device__ __forceinline__ void fma2(unsigned long long& d,
                                     unsigned long long a,
                                     unsigned long long b,
                                     unsigned long long c) {
    asm("fma.rn.f32x2 %0, %1, %2, %3;" : "=l"(d) : "l"(a), "l"(b), "l"(c));
}

__device__ __forceinline__ void lds_v2b64(unsigned long long& a,
                                          unsigned long long& b,
                                          unsigned int addr) {
    asm volatile("ld.shared.v2.b64 {%0, %1}, [%2];"
                 : "=l"(a), "=l"(b) : "r"(addr));
}

__device__ __forceinline__ void ldg_v2b64(unsigned long long& a,
                                          unsigned long long& b,
                                          const void* p) {
    asm volatile("ld.global.nc.v2.b64 {%0, %1}, [%2];"
                 : "=l"(a), "=l"(b) : "l"(p));
}

__device__ __forceinline__ float unpack_add(unsigned long long v) {
    float lo, hi;
    asm("mov.b64 {%0, %1}, %2;" : "=f"(lo), "=f"(hi) : "l"(v));
    return lo + hi;
}

__device__ __forceinline__ unsigned int smem_addr_u32(const void* p) {
    unsigned int a;
    asm("{ .reg .u64 t; cvta.to.shared.u64 t, %1; cvt.u32.u64 %0, t; }"
        : "=r"(a) : "l"(p));
    return a;
}

// ---------------------------------------------------------------------------
// Kernel 1: fused  (a) zero d_out + g_deg,  (b) hW = h @ W
// 4 threads per node, 8 output features each. W transposed in smem:
// sWt[j*64 + k] = W[k][j]  -> consecutive-k pairs feed fma.rn.f32x2 directly.
// ---------------------------------------------------------------------------
__global__ void __launch_bounds__(256) gemm_zero_kernel(
        const float* __restrict__ h,
        const float* __restrict__ W,
        float*       __restrict__ out) {
    __shared__ float sWt[OUT_FEATS * IN_FEATS];   // 8 KB, transposed

    // stage W transposed: read strided from global, write linear to smem
    for (int i = threadIdx.x; i < OUT_FEATS * IN_FEATS; i += blockDim.x) {
        int j = i >> 6;        // output feature
        int k = i & 63;        // input feature
        sWt[i] = __ldg(W + k * OUT_FEATS + j);
    }

    // grid-stride zero of out (float4) and g_deg
    {
        int tg     = blockIdx.x * blockDim.x + threadIdx.x;
        int stride = gridDim.x * blockDim.x;
        float4 z = make_float4(0.f, 0.f, 0.f, 0.f);
        float4* out4 = reinterpret_cast<float4*>(out);
        for (int i = tg; i < N_NODES * OUT_FEATS / 4; i += stride)
            out4[i] = z;
        for (int i = tg; i < N_NODES; i += stride)
            g_deg[i] = 0.0f;
    }
    __syncthreads();

    int t    = blockIdx.x * blockDim.x + threadIdx.x;
    int node = t >> 2;          // 4 threads per node
    int jg   = t & 3;           // which block of 8 output features
    if (node >= N_NODES) return;

    const float* hrow = h + (size_t)node * IN_FEATS;
    unsigned int wbase = smem_addr_u32(sWt) + (unsigned)(jg * 8) * IN_FEATS * 4;

    // acc2[jj] holds (sum over even k, sum over odd k) for output j = jg*8+jj
    unsigned long long acc2[8];
    #pragma unroll
    for (int jj = 0; jj < 8; jj++) acc2[jj] = 0ull;

    #pragma unroll 4
    for (int k4 = 0; k4 < IN_FEATS / 4; k4++) {
        // h[k4*4 .. k4*4+3] as two packed f32x2
        unsigned long long h01, h23;
        ldg_v2b64(h01, h23, hrow + k4 * 4);

        unsigned int ka = wbase + (unsigned)(k4 * 4) * 4;  // byte offset of k within row
        #pragma unroll
        for (int jj = 0; jj < 8; jj++) {
            unsigned long long w01, w23;
            lds_v2b64(w01, w23, ka + (unsigned)jj * IN_FEATS * 4);
            fma2(acc2[jj], h01, w01, acc2[jj]);
            fma2(acc2[jj], h23, w23, acc2[jj]);
        }
    }

    // reduce pairs and store 8 contiguous outputs (two float4)
    float r[8];
    #pragma unroll
    for (int jj = 0; jj < 8; jj++) r[jj] = unpack_add(acc2[jj]);

    float4* orow = reinterpret_cast<float4*>(g_hW + (size_t)node * OUT_FEATS + jg * 8);
    orow[0] = make_float4(r[0], r[1], r[2], r[3]);
    orow[1] = make_float4(r[4], r[5], r[6], r[7]);
}

// ---------------------------------------------------------------------------
// Kernel 2: edge scatter. 8 threads per edge, one red.global.add.v4.f32 each.
// ---------------------------------------------------------------------------
__global__ void __launch_bounds__(256) scatter_kernel(
        const int*   __restrict__ src,
        const int*   __restrict__ dst,
        const float* __restrict__ order,
        float*       __restrict__ agg) {
    int t   = blockIdx.x * blockDim.x + threadIdx.x;
    int e   = t >> 3;
    int sub = t & 7;
    if (e >= N_EDGES) return;

    int   s = __ldg(src + e);
    int   d = __ldg(dst + e);
    float w = __ldg(order + e);

    float4 v = __ldg(reinterpret_cast<const float4*>(
                         g_hW + (size_t)s * OUT_FEATS + sub * 4));
    v.x *= w; v.y *= w; v.z *= w; v.w *= w;

    float* a = agg + (size_t)d * OUT_FEATS + sub * 4;
    asm volatile("red.global.add.v4.f32 [%0], {%1, %2, %3, %4};"
                 :: "l"(a), "f"(v.x), "f"(v.y), "f"(v.z), "f"(v.w)
                 : "memory");

    if (sub == 0)
        atomicAdd(g_deg + d, 1.0f);
}

// ---------------------------------------------------------------------------
// Kernel 3: out = relu(agg/max(deg,1) + b), in place, float4-vectorized.
// ---------------------------------------------------------------------------
__global__ void __launch_bounds__(256) finalize_kernel(
        float* __restrict__ out,
        const float* __restrict__ b) {
    int t = blockIdx.x * blockDim.x + threadIdx.x;   // float4 index
    if (t >= N_NODES * OUT_FEATS / 4) return;
    int n  = t >> 3;   // node
    int j4 = t & 7;    // float4 within row

    float  deg  = __ldg(g_deg + n);
    float  norm = 1.0f / fmaxf(deg, 1.0f);
    float4 bb   = __ldg(reinterpret_cast<const float4*>(b) + j4);

    float4* out4 = reinterpret_cast<float4*>(out);
    float4 v = out4[t];
    v.x = fmaxf(fmaf(v.x, norm, bb.x), 0.0f);
    v.y = fmaxf(fmaf(v.y, norm, bb.y), 0.0f);
    v.z = fmaxf(fmaf(v.z, norm, bb.z), 0.0f);
    v.w = fmaxf(fmaf(v.w, norm, bb.w), 0.0f);
    out4[t] = v;
}

// ---------------------------------------------------------------------------
// Launch
// ---------------------------------------------------------------------------
extern "C" void kernel_launch(void* const* d_in, const int* in_sizes, int n_in,
                              void* d_out, int out_size) {
    const float* h     = (const float*)d_in[0];
    const int*   src   = (const int*)  d_in[1];
    const int*   dst   = (const int*)  d_in[2];
    const float* order = (const float*)d_in[3];
    const float* W     = (const float*)d_in[4];
    const float* b     = (const float*)d_in[5];
    float*       out   = (float*)d_out;

    (void)in_sizes; (void)n_in; (void)out_size;

    // 4 threads per node
    {
        long long total = (long long)N_NODES * 4;
        int blocks = (int)((total + 255) / 256);
        gemm_zero_kernel<<<blocks, 256>>>(h, W, out);
    }

    {
        long long total = (long long)N_EDGES * 8;
        int blocks = (int)((total + 255) / 256);
        scatter_kernel<<<blocks, 256>>>(src, dst, order, out);
    }

    finalize_kernel<<<(N_NODES * OUT_FEATS / 4 + 255) / 256, 256>>>(out, b);
}

// round 4
// speedup vs baseline: 1.9783x; 1.9783x over previous
#include <cuda_runtime.h>
#include <cstdint>

#define N_NODES   100000
#define N_EDGES   1600000
#define IN_FEATS  64
#define OUT_FEATS 32
#define NODE_QUADS ((N_NODES + 3) / 4)

// Scratch (no cudaMalloc allowed)
__device__ float g_hW[N_NODES * OUT_FEATS];   // 12.8 MB
__device__ float g_deg[N_NODES];              // 0.4 MB

// ---------------------------------------------------------------------------
// Kernel 1: fused  (a) zero d_out + g_deg,  (b) hW = h @ W
// Register tiling: each thread computes a 4-node x 8-feature tile.
// Per scalar k: 2 LDS.128 of W shared across 4 nodes -> 32 FMAs (1B smem/FMA).
// ---------------------------------------------------------------------------
__global__ void __launch_bounds__(256) gemm_zero_kernel(
        const float* __restrict__ h,
        const float* __restrict__ W,
        float*       __restrict__ out) {
    __shared__ float4 sW4[IN_FEATS * OUT_FEATS / 4];   // natural layout, 8 KB

    // stage W (row-major [k][j], straight float4 copy)
    {
        const float4* W4 = reinterpret_cast<const float4*>(W);
        for (int i = threadIdx.x; i < IN_FEATS * OUT_FEATS / 4; i += blockDim.x)
            sW4[i] = W4[i];
    }

    // grid-stride zero of out (float4) and g_deg
    {
        int tg     = blockIdx.x * blockDim.x + threadIdx.x;
        int stride = gridDim.x * blockDim.x;
        float4 z = make_float4(0.f, 0.f, 0.f, 0.f);
        float4* out4 = reinterpret_cast<float4*>(out);
        for (int i = tg; i < N_NODES * OUT_FEATS / 4; i += stride)
            out4[i] = z;
        for (int i = tg; i < N_NODES; i += stride)
            g_deg[i] = 0.0f;
    }
    __syncthreads();

    int t  = blockIdx.x * blockDim.x + threadIdx.x;
    int nq = t >> 2;            // node quad (4 nodes)
    int jg = t & 3;             // 8-feature group
    if (nq >= NODE_QUADS) return;

    int node0 = nq * 4;
    // N_NODES = 100000 divisible by 4, so all 4 nodes valid.
    const float* hbase = h + (size_t)node0 * IN_FEATS;

    float acc[4][8];
    #pragma unroll
    for (int i = 0; i < 4; i++)
        #pragma unroll
        for (int j = 0; j < 8; j++) acc[i][j] = 0.0f;

    #pragma unroll 2
    for (int k4 = 0; k4 < IN_FEATS / 4; k4++) {
        // h[node0+i][k4*4 .. +3]
        float4 hv[4];
        #pragma unroll
        for (int i = 0; i < 4; i++)
            hv[i] = __ldg(reinterpret_cast<const float4*>(
                              hbase + (size_t)i * IN_FEATS + k4 * 4));

        #pragma unroll
        for (int kk = 0; kk < 4; kk++) {
            int k = k4 * 4 + kk;
            float4 w0 = sW4[k * (OUT_FEATS / 4) + jg * 2 + 0];
            float4 w1 = sW4[k * (OUT_FEATS / 4) + jg * 2 + 1];
            #pragma unroll
            for (int i = 0; i < 4; i++) {
                float hk = (kk == 0) ? hv[i].x : (kk == 1) ? hv[i].y
                         : (kk == 2) ? hv[i].z : hv[i].w;
                acc[i][0] = fmaf(hk, w0.x, acc[i][0]);
                acc[i][1] = fmaf(hk, w0.y, acc[i][1]);
                acc[i][2] = fmaf(hk, w0.z, acc[i][2]);
                acc[i][3] = fmaf(hk, w0.w, acc[i][3]);
                acc[i][4] = fmaf(hk, w1.x, acc[i][4]);
                acc[i][5] = fmaf(hk, w1.y, acc[i][5]);
                acc[i][6] = fmaf(hk, w1.z, acc[i][6]);
                acc[i][7] = fmaf(hk, w1.w, acc[i][7]);
            }
        }
    }

    #pragma unroll
    for (int i = 0; i < 4; i++) {
        float4* orow = reinterpret_cast<float4*>(
            g_hW + (size_t)(node0 + i) * OUT_FEATS + jg * 8);
        orow[0] = make_float4(acc[i][0], acc[i][1], acc[i][2], acc[i][3]);
        orow[1] = make_float4(acc[i][4], acc[i][5], acc[i][6], acc[i][7]);
    }
}

// ---------------------------------------------------------------------------
// Kernel 2: edge scatter. 8 threads per edge, one red.global.add.v4.f32 each.
// ---------------------------------------------------------------------------
__global__ void __launch_bounds__(256) scatter_kernel(
        const int*   __restrict__ src,
        const int*   __restrict__ dst,
        const float* __restrict__ order,
        float*       __restrict__ agg) {
    int t   = blockIdx.x * blockDim.x + threadIdx.x;
    int e   = t >> 3;
    int sub = t & 7;
    if (e >= N_EDGES) return;

    int   s = __ldg(src + e);
    int   d = __ldg(dst + e);
    float w = __ldg(order + e);

    float4 v = __ldg(reinterpret_cast<const float4*>(
                         g_hW + (size_t)s * OUT_FEATS + sub * 4));
    v.x *= w; v.y *= w; v.z *= w; v.w *= w;

    float* a = agg + (size_t)d * OUT_FEATS + sub * 4;
    asm volatile("red.global.add.v4.f32 [%0], {%1, %2, %3, %4};"
                 :: "l"(a), "f"(v.x), "f"(v.y), "f"(v.z), "f"(v.w)
                 : "memory");

    if (sub == 0)
        atomicAdd(g_deg + d, 1.0f);
}

// ---------------------------------------------------------------------------
// Kernel 3: out = relu(agg/max(deg,1) + b), in place, float4-vectorized.
// ---------------------------------------------------------------------------
__global__ void __launch_bounds__(256) finalize_kernel(
        float* __restrict__ out,
        const float* __restrict__ b) {
    int t = blockIdx.x * blockDim.x + threadIdx.x;   // float4 index
    if (t >= N_NODES * OUT_FEATS / 4) return;
    int n  = t >> 3;   // node
    int j4 = t & 7;    // float4 within row

    float  deg  = __ldg(g_deg + n);
    float  norm = 1.0f / fmaxf(deg, 1.0f);
    float4 bb   = __ldg(reinterpret_cast<const float4*>(b) + j4);

    float4* out4 = reinterpret_cast<float4*>(out);
    float4 v = out4[t];
    v.x = fmaxf(fmaf(v.x, norm, bb.x), 0.0f);
    v.y = fmaxf(fmaf(v.y, norm, bb.y), 0.0f);
    v.z = fmaxf(fmaf(v.z, norm, bb.z), 0.0f);
    v.w = fmaxf(fmaf(v.w, norm, bb.w), 0.0f);
    out4[t] = v;
}

// ---------------------------------------------------------------------------
// Launch
// ---------------------------------------------------------------------------
extern "C" void kernel_launch(void* const* d_in, const int* in_sizes, int n_in,
                              void* d_out, int out_size) {
    const float* h     = (const float*)d_in[0];
    const int*   src   = (const int*)  d_in[1];
    const int*   dst   = (const int*)  d_in[2];
    const float* order = (const float*)d_in[3];
    const float* W     = (const float*)d_in[4];
    const float* b     = (const float*)d_in[5];
    float*       out   = (float*)d_out;

    (void)in_sizes; (void)n_in; (void)out_size;

    // 1 thread per (node quad, jg) -> 100K threads
    {
        long long total = (long long)NODE_QUADS * 4;
        int blocks = (int)((total + 255) / 256);
        gemm_zero_kernel<<<blocks, 256>>>(h, W, out);
    }

    {
        long long total = (long long)N_EDGES * 8;
        int blocks = (int)((total + 255) / 256);
        scatter_kernel<<<blocks, 256>>>(src, dst, order, out);
    }

    finalize_kernel<<<(N_NODES * OUT_FEATS / 4 + 255) / 256, 256>>>(out, b);
}

// round 5
// speedup vs baseline: 2.8359x; 1.4335x over previous
#include <cuda_runtime.h>
#include <cstdint>

#define N_NODES   100000
#define N_EDGES   1600000
#define IN_FEATS  64
#define OUT_FEATS 32
#define NODE_PAIRS (N_NODES / 2)   // 100000 is even

// Scratch (no cudaMalloc allowed)
__device__ float g_hW[N_NODES * OUT_FEATS];   // 12.8 MB
__device__ float g_deg[N_NODES];              // 0.4 MB

// ---------------------------------------------------------------------------
// Kernel 1: fused  (a) zero d_out + g_deg,  (b) hW = h @ W
// Register tiling: each thread computes a 2-node x 8-feature tile.
// 200K threads -> 782 blocks -> ~5.3 blocks/SM (occupancy fix vs round 4).
// Per scalar k: 2 LDS.128 of W shared across 2 nodes -> 16 FMAs (2B smem/FMA).
// ---------------------------------------------------------------------------
__global__ void __launch_bounds__(256) gemm_zero_kernel(
        const float* __restrict__ h,
        const float* __restrict__ W,
        float*       __restrict__ out) {
    __shared__ float4 sW4[IN_FEATS * OUT_FEATS / 4];   // 8 KB, natural [k][j]

    // stage W
    {
        const float4* W4 = reinterpret_cast<const float4*>(W);
        for (int i = threadIdx.x; i < IN_FEATS * OUT_FEATS / 4; i += blockDim.x)
            sW4[i] = W4[i];
    }

    // grid-stride zero of out (float4) and g_deg
    {
        int tg     = blockIdx.x * blockDim.x + threadIdx.x;
        int stride = gridDim.x * blockDim.x;
        float4 z = make_float4(0.f, 0.f, 0.f, 0.f);
        float4* out4 = reinterpret_cast<float4*>(out);
        for (int i = tg; i < N_NODES * OUT_FEATS / 4; i += stride)
            out4[i] = z;
        for (int i = tg; i < N_NODES; i += stride)
            g_deg[i] = 0.0f;
    }
    __syncthreads();

    int t  = blockIdx.x * blockDim.x + threadIdx.x;
    int np = t >> 2;            // node pair
    int jg = t & 3;             // 8-feature group
    if (np >= NODE_PAIRS) return;

    int node0 = np * 2;
    const float* hbase = h + (size_t)node0 * IN_FEATS;

    float acc[2][8];
    #pragma unroll
    for (int i = 0; i < 2; i++)
        #pragma unroll
        for (int j = 0; j < 8; j++) acc[i][j] = 0.0f;

    #pragma unroll 4
    for (int k4 = 0; k4 < IN_FEATS / 4; k4++) {
        float4 hv[2];
        hv[0] = __ldg(reinterpret_cast<const float4*>(hbase + k4 * 4));
        hv[1] = __ldg(reinterpret_cast<const float4*>(hbase + IN_FEATS + k4 * 4));

        #pragma unroll
        for (int kk = 0; kk < 4; kk++) {
            int k = k4 * 4 + kk;
            float4 w0 = sW4[k * (OUT_FEATS / 4) + jg * 2 + 0];
            float4 w1 = sW4[k * (OUT_FEATS / 4) + jg * 2 + 1];
            #pragma unroll
            for (int i = 0; i < 2; i++) {
                float hk = (kk == 0) ? hv[i].x : (kk == 1) ? hv[i].y
                         : (kk == 2) ? hv[i].z : hv[i].w;
                acc[i][0] = fmaf(hk, w0.x, acc[i][0]);
                acc[i][1] = fmaf(hk, w0.y, acc[i][1]);
                acc[i][2] = fmaf(hk, w0.z, acc[i][2]);
                acc[i][3] = fmaf(hk, w0.w, acc[i][3]);
                acc[i][4] = fmaf(hk, w1.x, acc[i][4]);
                acc[i][5] = fmaf(hk, w1.y, acc[i][5]);
                acc[i][6] = fmaf(hk, w1.z, acc[i][6]);
                acc[i][7] = fmaf(hk, w1.w, acc[i][7]);
            }
        }
    }

    #pragma unroll
    for (int i = 0; i < 2; i++) {
        float4* orow = reinterpret_cast<float4*>(
            g_hW + (size_t)(node0 + i) * OUT_FEATS + jg * 8);
        orow[0] = make_float4(acc[i][0], acc[i][1], acc[i][2], acc[i][3]);
        orow[1] = make_float4(acc[i][4], acc[i][5], acc[i][6], acc[i][7]);
    }
}

// ---------------------------------------------------------------------------
// Kernel 2: edge scatter. 8 threads per edge, one red.global.add.v4.f32 each.
// ---------------------------------------------------------------------------
__global__ void __launch_bounds__(256) scatter_kernel(
        const int*   __restrict__ src,
        const int*   __restrict__ dst,
        const float* __restrict__ order,
        float*       __restrict__ agg) {
    int t   = blockIdx.x * blockDim.x + threadIdx.x;
    int e   = t >> 3;
    int sub = t & 7;
    if (e >= N_EDGES) return;

    int   s = __ldg(src + e);
    int   d = __ldg(dst + e);
    float w = __ldg(order + e);

    float4 v = __ldg(reinterpret_cast<const float4*>(
                         g_hW + (size_t)s * OUT_FEATS + sub * 4));
    v.x *= w; v.y *= w; v.z *= w; v.w *= w;

    float* a = agg + (size_t)d * OUT_FEATS + sub * 4;
    asm volatile("red.global.add.v4.f32 [%0], {%1, %2, %3, %4};"
                 :: "l"(a), "f"(v.x), "f"(v.y), "f"(v.z), "f"(v.w)
                 : "memory");

    if (sub == 0)
        atomicAdd(g_deg + d, 1.0f);
}

// ---------------------------------------------------------------------------
// Kernel 3: out = relu(agg/max(deg,1) + b), in place, float4-vectorized.
// ---------------------------------------------------------------------------
__global__ void __launch_bounds__(256) finalize_kernel(
        float* __restrict__ out,
        const float* __restrict__ b) {
    int t = blockIdx.x * blockDim.x + threadIdx.x;   // float4 index
    if (t >= N_NODES * OUT_FEATS / 4) return;
    int n  = t >> 3;   // node
    int j4 = t & 7;    // float4 within row

    float  deg  = __ldg(g_deg + n);
    float  norm = 1.0f / fmaxf(deg, 1.0f);
    float4 bb   = __ldg(reinterpret_cast<const float4*>(b) + j4);

    float4* out4 = reinterpret_cast<float4*>(out);
    float4 v = out4[t];
    v.x = fmaxf(fmaf(v.x, norm, bb.x), 0.0f);
    v.y = fmaxf(fmaf(v.y, norm, bb.y), 0.0f);
    v.z = fmaxf(fmaf(v.z, norm, bb.z), 0.0f);
    v.w = fmaxf(fmaf(v.w, norm, bb.w), 0.0f);
    out4[t] = v;
}

// ---------------------------------------------------------------------------
// Launch
// ---------------------------------------------------------------------------
extern "C" void kernel_launch(void* const* d_in, const int* in_sizes, int n_in,
                              void* d_out, int out_size) {
    const float* h     = (const float*)d_in[0];
    const int*   src   = (const int*)  d_in[1];
    const int*   dst   = (const int*)  d_in[2];
    const float* order = (const float*)d_in[3];
    const float* W     = (const float*)d_in[4];
    const float* b     = (const float*)d_in[5];
    float*       out   = (float*)d_out;

    (void)in_sizes; (void)n_in; (void)out_size;

    // 4 threads per node pair -> 200K threads
    {
        long long total = (long long)NODE_PAIRS * 4;
        int blocks = (int)((total + 255) / 256);
        gemm_zero_kernel<<<blocks, 256>>>(h, W, out);
    }

    {
        long long total = (long long)N_EDGES * 8;
        int blocks = (int)((total + 255) / 256);
        scatter_kernel<<<blocks, 256>>>(src, dst, order, out);
    }

    finalize_kernel<<<(N_NODES * OUT_FEATS / 4 + 255) / 256, 256>>>(out, b);
}